// round 2
// baseline (speedup 1.0000x reference)
#include <cuda_runtime.h>

namespace {
constexpr int IMG_H = 512, IMG_W = 512, CH = 3, NB = 2;
constexpr int TW = 32, TH = 16, HALO = 3;
constexpr int SMW = TW + 2 * HALO;   // 38
constexpr int SMH = TH + 2 * HALO;   // 22
constexpr float L2E = 1.4426950408889634f;          // log2(e)
constexpr float C50L2E = 72.13475204444817f;        // 50 * log2(e)
}

__device__ __forceinline__ float ex2f(float v) {
    float r;
    asm("ex2.approx.f32 %0, %1;" : "=f"(r) : "f"(v));
    return r;
}
__device__ __forceinline__ float rcpf(float v) {
    float r;
    asm("rcp.approx.f32 %0, %1;" : "=f"(r) : "f"(v));
    return r;
}
__device__ __forceinline__ int refl(int p, int n) {
    return p < 0 ? -p : (p >= n ? 2 * n - 2 - p : p);
}

__global__ __launch_bounds__(256, 2)
void afilt_kernel(const float* __restrict__ xin,
                  const float* __restrict__ gin,
                  const float* __restrict__ w0,
                  float* __restrict__ out)
{
    __shared__ float sg[CH][SMH][SMW];
    __shared__ float sx[CH][SMH][SMW];

    const int tx = threadIdx.x & 31;
    const int ty = threadIdx.x >> 5;            // 0..7, owns 2 vertical pixels
    const int bx = blockIdx.x * TW;
    const int by = blockIdx.y * TH;
    const int b  = blockIdx.z;

    // Cooperative reflect-padded tile fill (guidance + x, 3 channels each)
    for (int idx = threadIdx.x; idx < SMH * SMW; idx += 256) {
        const int r = idx / SMW;
        const int c = idx - r * SMW;
        const int gy = refl(by + r - HALO, IMG_H);
        const int gx = refl(bx + c - HALO, IMG_W);
        #pragma unroll
        for (int ch = 0; ch < CH; ch++) {
            const size_t off = (((size_t)b * CH + ch) * IMG_H + gy) * IMG_W + gx;
            sg[ch][r][c] = gin[off];
            sx[ch][r][c] = xin[off];
        }
    }

    const int px  = bx + tx;
    const int pyA = by + ty * 2;

    // Per-pixel half-kernel logits: 16 contiguous floats per pixel.
    const float4* wA4 = reinterpret_cast<const float4*>(w0)
                      + ((size_t)b * IMG_H * IMG_W + (size_t)pyA * IMG_W + px) * 4;
    const float4* wB4 = wA4 + (size_t)IMG_W * 4;

    float wa[16], wb[16];
    {
        float4 t;
        t = wA4[0]; wa[0]=t.x;  wa[1]=t.y;  wa[2]=t.z;  wa[3]=t.w;
        t = wA4[1]; wa[4]=t.x;  wa[5]=t.y;  wa[6]=t.z;  wa[7]=t.w;
        t = wA4[2]; wa[8]=t.x;  wa[9]=t.y;  wa[10]=t.z; wa[11]=t.w;
        t = wA4[3]; wa[12]=t.x; wa[13]=t.y; wa[14]=t.z; wa[15]=t.w;
        t = wB4[0]; wb[0]=t.x;  wb[1]=t.y;  wb[2]=t.z;  wb[3]=t.w;
        t = wB4[1]; wb[4]=t.x;  wb[5]=t.y;  wb[6]=t.z;  wb[7]=t.w;
        t = wB4[2]; wb[8]=t.x;  wb[9]=t.y;  wb[10]=t.z; wb[11]=t.w;
        t = wB4[3]; wb[12]=t.x; wb[13]=t.y; wb[14]=t.z; wb[15]=t.w;
    }
    // Softmax Z and the max-shift cancel in num/den; keep max-shift for range safety
    // and pre-scale by log2(e) so each tap is a single FFMA + MUFU.EX2.
    float mA = wa[0], mB = wb[0];
    #pragma unroll
    for (int i = 1; i < 16; i++) { mA = fmaxf(mA, wa[i]); mB = fmaxf(mB, wb[i]); }
    #pragma unroll
    for (int i = 0; i < 16; i++) {
        wa[i] = (wa[i] - mA) * L2E;
        wb[i] = (wb[i] - mB) * L2E;
    }

    __syncthreads();

    const int sy = ty * 2;
    const float cA0 = sg[0][sy + HALO][tx + HALO];
    const float cA1 = sg[1][sy + HALO][tx + HALO];
    const float cA2 = sg[2][sy + HALO][tx + HALO];
    const float cB0 = sg[0][sy + HALO + 1][tx + HALO];
    const float cB1 = sg[1][sy + HALO + 1][tx + HALO];
    const float cB2 = sg[2][sy + HALO + 1][tx + HALO];

    float nA0 = 0.f, nA1 = 0.f, nA2 = 0.f, dA = 0.f;
    float nB0 = 0.f, nB1 = 0.f, nB2 = 0.f, dB = 0.f;

    // 8 shared rows serve both vertical pixels (rows 0..6 -> A, 1..7 -> B).
    #pragma unroll
    for (int r = 0; r < 8; r++) {
        #pragma unroll
        for (int j = 0; j < 7; j++) {
            const float g0 = sg[0][sy + r][tx + j];
            const float g1 = sg[1][sy + r][tx + j];
            const float g2 = sg[2][sy + r][tx + j];
            const float v0 = sx[0][sy + r][tx + j];
            const float v1 = sx[1][sy + r][tx + j];
            const float v2 = sx[2][sy + r][tx + j];
            const int mj = (j < 4) ? j : 6 - j;     // reflect map of full kernel col
            if (r < 7) {
                const int mi = (r < 4) ? r : 6 - r;
                const float s = fabsf(g0 - cA0) + fabsf(g1 - cA1) + fabsf(g2 - cA2);
                const float e = ex2f(wa[mi * 4 + mj] - C50L2E * (s * s));
                nA0 += v0 * e; nA1 += v1 * e; nA2 += v2 * e; dA += e;
            }
            if (r >= 1) {
                const int i2 = r - 1;
                const int mi = (i2 < 4) ? i2 : 6 - i2;
                const float s = fabsf(g0 - cB0) + fabsf(g1 - cB1) + fabsf(g2 - cB2);
                const float e = ex2f(wb[mi * 4 + mj] - C50L2E * (s * s));
                nB0 += v0 * e; nB1 += v1 * e; nB2 += v2 * e; dB += e;
            }
        }
    }

    const float iA = rcpf(dA);
    const float iB = rcpf(dB);

    const size_t hw = (size_t)IMG_H * IMG_W;
    const size_t ob = (size_t)b * CH * hw + (size_t)pyA * IMG_W + px;
    out[ob]               = nA0 * iA;
    out[ob + hw]          = nA1 * iA;
    out[ob + 2 * hw]      = nA2 * iA;
    out[ob + IMG_W]           = nB0 * iB;
    out[ob + IMG_W + hw]      = nB1 * iB;
    out[ob + IMG_W + 2 * hw]  = nB2 * iB;
}

extern "C" void kernel_launch(void* const* d_in, const int* in_sizes, int n_in,
                              void* d_out, int out_size)
{
    const float* x  = (const float*)d_in[0];
    const float* g  = (const float*)d_in[1];
    const float* w0 = (const float*)d_in[2];
    float* out = (float*)d_out;

    dim3 grid(IMG_W / TW, IMG_H / TH, NB);   // 16 x 32 x 2
    dim3 block(256);
    afilt_kernel<<<grid, block>>>(x, g, w0, out);
}

// round 4
// speedup vs baseline: 1.1648x; 1.1648x over previous
#include <cuda_runtime.h>

namespace {
constexpr int IMG_H = 512, IMG_W = 512, CH = 3, NB = 2;
constexpr int TW = 32, TH = 16, HALO = 3;
constexpr int SMW = TW + 2 * HALO;   // 38
constexpr int SMH = TH + 2 * HALO;   // 22
constexpr float L2E = 1.4426950408889634f;          // log2(e)
constexpr float C50L2E = 72.13475204444817f;        // 50 * log2(e)
}

__device__ __forceinline__ float ex2f(float v) {
    float r;
    asm("ex2.approx.f32 %0, %1;" : "=f"(r) : "f"(v));
    return r;
}
__device__ __forceinline__ float rcpf(float v) {
    float r;
    asm("rcp.approx.f32 %0, %1;" : "=f"(r) : "f"(v));
    return r;
}
__device__ __forceinline__ int refl(int p, int n) {
    return p < 0 ? -p : (p >= n ? 2 * n - 2 - p : p);
}

__global__ __launch_bounds__(256, 3)
void afilt_kernel(const float* __restrict__ xin,
                  const float* __restrict__ gin,
                  const float* __restrict__ w0,
                  float* __restrict__ out)
{
    // Packed per-pixel tiles: one LDS.128 + one LDS.64 fetch everything for a tap.
    __shared__ float4 sA[SMH][SMW];   // {g0, g1, g2, x0}
    __shared__ float2 sB[SMH][SMW];   // {x1, x2}

    const int tx = threadIdx.x & 31;
    const int ty = threadIdx.x >> 5;            // 0..7, owns 2 vertical pixels
    const int bx = blockIdx.x * TW;
    const int by = blockIdx.y * TH;
    const int b  = blockIdx.z;

    const size_t hw = (size_t)IMG_H * IMG_W;

    // Cooperative reflect-padded tile fill
    for (int idx = threadIdx.x; idx < SMH * SMW; idx += 256) {
        const int r = idx / SMW;
        const int c = idx - r * SMW;
        const int gy = refl(by + r - HALO, IMG_H);
        const int gx = refl(bx + c - HALO, IMG_W);
        const size_t off = (size_t)b * CH * hw + (size_t)gy * IMG_W + gx;
        float4 a;
        a.x = gin[off];
        a.y = gin[off + hw];
        a.z = gin[off + 2 * hw];
        a.w = xin[off];
        float2 v;
        v.x = xin[off + hw];
        v.y = xin[off + 2 * hw];
        sA[r][c] = a;
        sB[r][c] = v;
    }

    const int px  = bx + tx;
    const int pyA = by + ty * 2;

    // Per-pixel half-kernel logits: 16 contiguous floats per pixel.
    const float4* wA4 = reinterpret_cast<const float4*>(w0)
                      + ((size_t)b * IMG_H * IMG_W + (size_t)pyA * IMG_W + px) * 4;
    const float4* wB4 = wA4 + (size_t)IMG_W * 4;

    float wa[16], wb[16];
    {
        float4 t;
        t = wA4[0]; wa[0]=t.x;  wa[1]=t.y;  wa[2]=t.z;  wa[3]=t.w;
        t = wA4[1]; wa[4]=t.x;  wa[5]=t.y;  wa[6]=t.z;  wa[7]=t.w;
        t = wA4[2]; wa[8]=t.x;  wa[9]=t.y;  wa[10]=t.z; wa[11]=t.w;
        t = wA4[3]; wa[12]=t.x; wa[13]=t.y; wa[14]=t.z; wa[15]=t.w;
        t = wB4[0]; wb[0]=t.x;  wb[1]=t.y;  wb[2]=t.z;  wb[3]=t.w;
        t = wB4[1]; wb[4]=t.x;  wb[5]=t.y;  wb[6]=t.z;  wb[7]=t.w;
        t = wB4[2]; wb[8]=t.x;  wb[9]=t.y;  wb[10]=t.z; wb[11]=t.w;
        t = wB4[3]; wb[12]=t.x; wb[13]=t.y; wb[14]=t.z; wb[15]=t.w;
    }
    // Softmax Z and max-shift cancel in num/den; keep the shift for range safety,
    // pre-scale by log2(e) so each tap is FFMA + MUFU.EX2.
    float mA = wa[0], mB = wb[0];
    #pragma unroll
    for (int i = 1; i < 16; i++) { mA = fmaxf(mA, wa[i]); mB = fmaxf(mB, wb[i]); }
    #pragma unroll
    for (int i = 0; i < 16; i++) {
        wa[i] = (wa[i] - mA) * L2E;
        wb[i] = (wb[i] - mB) * L2E;
    }

    __syncthreads();

    const int sy = ty * 2;
    const float4 ctrA = sA[sy + HALO][tx + HALO];
    const float4 ctrB = sA[sy + HALO + 1][tx + HALO];

    float nA0 = 0.f, nA1 = 0.f, nA2 = 0.f, dA = 0.f;
    float nB0 = 0.f, nB1 = 0.f, nB2 = 0.f, dB = 0.f;

    // 8 shared rows serve both vertical pixels (rows 0..6 -> A, 1..7 -> B).
    #pragma unroll
    for (int r = 0; r < 8; r++) {
        #pragma unroll
        for (int j = 0; j < 7; j++) {
            const float4 a  = sA[sy + r][tx + j];   // g0,g1,g2,x0
            const float2 vv = sB[sy + r][tx + j];   // x1,x2
            const int mj = (j < 4) ? j : 6 - j;     // reflect map of full kernel col
            if (r < 7) {
                const int mi = (r < 4) ? r : 6 - r;
                const float s = fabsf(a.x - ctrA.x) + fabsf(a.y - ctrA.y)
                              + fabsf(a.z - ctrA.z);
                const float e = ex2f(wa[mi * 4 + mj] - C50L2E * (s * s));
                nA0 += a.w  * e;
                nA1 += vv.x * e;
                nA2 += vv.y * e;
                dA  += e;
            }
            if (r >= 1) {
                const int i2 = r - 1;
                const int mi = (i2 < 4) ? i2 : 6 - i2;
                const float s = fabsf(a.x - ctrB.x) + fabsf(a.y - ctrB.y)
                              + fabsf(a.z - ctrB.z);
                const float e = ex2f(wb[mi * 4 + mj] - C50L2E * (s * s));
                nB0 += a.w  * e;
                nB1 += vv.x * e;
                nB2 += vv.y * e;
                dB  += e;
            }
        }
    }

    const float iA = rcpf(dA);
    const float iB = rcpf(dB);

    const size_t ob = (size_t)b * CH * hw + (size_t)pyA * IMG_W + px;
    out[ob]               = nA0 * iA;
    out[ob + hw]          = nA1 * iA;
    out[ob + 2 * hw]      = nA2 * iA;
    out[ob + IMG_W]           = nB0 * iB;
    out[ob + IMG_W + hw]      = nB1 * iB;
    out[ob + IMG_W + 2 * hw]  = nB2 * iB;
}

extern "C" void kernel_launch(void* const* d_in, const int* in_sizes, int n_in,
                              void* d_out, int out_size)
{
    const float* x  = (const float*)d_in[0];
    const float* g  = (const float*)d_in[1];
    const float* w0 = (const float*)d_in[2];
    float* out = (float*)d_out;

    dim3 grid(IMG_W / TW, IMG_H / TH, NB);   // 16 x 32 x 2
    dim3 block(256);
    afilt_kernel<<<grid, block>>>(x, g, w0, out);
}

// round 6
// speedup vs baseline: 1.2667x; 1.0875x over previous
#include <cuda_runtime.h>

namespace {
constexpr int IMG_H = 512, IMG_W = 512, CH = 3, NB = 2;
constexpr int TW = 32, TH = 16, HALO = 3;
constexpr int SMW = TW + 2 * HALO;   // 38
constexpr int SMH = TH + 2 * HALO;   // 22
constexpr float L2E = 1.4426950408889634f;          // log2(e)
constexpr float C50L2E = 72.13475204444817f;        // 50 * log2(e)
}

__device__ __forceinline__ float ex2f(float v) {
    float r;
    asm("ex2.approx.f32 %0, %1;" : "=f"(r) : "f"(v));
    return r;
}
__device__ __forceinline__ float rcpf(float v) {
    float r;
    asm("rcp.approx.f32 %0, %1;" : "=f"(r) : "f"(v));
    return r;
}
__device__ __forceinline__ int refl(int p, int n) {
    return p < 0 ? -p : (p >= n ? 2 * n - 2 - p : p);
}

__global__ __launch_bounds__(256, 4)
void afilt_kernel(const float* __restrict__ xin,
                  const float* __restrict__ gin,
                  const float* __restrict__ w0,
                  float* __restrict__ out)
{
    // Packed per-pixel tiles: one LDS.128 + one LDS.64 fetch everything for a tap.
    __shared__ float4 sA[SMH][SMW];   // {g0, g1, g2, x0}
    __shared__ float2 sB[SMH][SMW];   // {x1, x2}

    const int tx = threadIdx.x & 31;
    const int ty = threadIdx.x >> 5;            // 0..7, owns 2 vertical pixels
    const int bx = blockIdx.x * TW;
    const int by = blockIdx.y * TH;
    const int b  = blockIdx.z;

    const size_t hw = (size_t)IMG_H * IMG_W;

    // Cooperative reflect-padded tile fill
    for (int idx = threadIdx.x; idx < SMH * SMW; idx += 256) {
        const int r = idx / SMW;
        const int c = idx - r * SMW;
        const int gy = refl(by + r - HALO, IMG_H);
        const int gx = refl(bx + c - HALO, IMG_W);
        const size_t off = (size_t)b * CH * hw + (size_t)gy * IMG_W + gx;
        float4 a;
        a.x = gin[off];
        a.y = gin[off + hw];
        a.z = gin[off + 2 * hw];
        a.w = xin[off];
        float2 v;
        v.x = xin[off + hw];
        v.y = xin[off + 2 * hw];
        sA[r][c] = a;
        sB[r][c] = v;
    }

    const int px  = bx + tx;
    const int pyA = by + ty * 2;

    // Per-pixel half-kernel logits: 4 float4 rows per pixel, contiguous.
    // Softmax Z and the max-shift both cancel in num/den, and the logit range
    // (|w| <~ 6) is safe for direct exp2 — so the raw rows are loaded on demand
    // per kernel row, needing only 4 live weight registers per pixel.
    const float4* wA4 = reinterpret_cast<const float4*>(w0)
                      + ((size_t)b * IMG_H * IMG_W + (size_t)pyA * IMG_W + px) * 4;
    const float4* wB4 = wA4 + (size_t)IMG_W * 4;

    __syncthreads();

    const int sy = ty * 2;
    const float4 cA = sA[sy + HALO][tx + HALO];
    const float4 cB = sA[sy + HALO + 1][tx + HALO];

    float nA0 = 0.f, nA1 = 0.f, nA2 = 0.f, dA = 0.f;
    float nB0 = 0.f, nB1 = 0.f, nB2 = 0.f, dB = 0.f;

    // 8 shared rows serve both vertical pixels (rows 0..6 -> A, 1..7 -> B).
    #pragma unroll
    for (int r = 0; r < 8; r++) {
        float4 wrA, wrB;
        if (r < 7) {
            const int mi = (r < 4) ? r : 6 - r;
            wrA = wA4[mi];
            wrA.x *= L2E; wrA.y *= L2E; wrA.z *= L2E; wrA.w *= L2E;
        }
        if (r >= 1) {
            const int i2 = r - 1;
            const int mi = (i2 < 4) ? i2 : 6 - i2;
            wrB = wB4[mi];
            wrB.x *= L2E; wrB.y *= L2E; wrB.z *= L2E; wrB.w *= L2E;
        }
        #pragma unroll
        for (int j = 0; j < 7; j++) {
            const float4 a  = sA[sy + r][tx + j];   // g0,g1,g2,x0
            const float2 vv = sB[sy + r][tx + j];   // x1,x2
            const int mj = (j < 4) ? j : 6 - j;     // reflect map of full kernel col
            if (r < 7) {
                const float s = fabsf(a.x - cA.x) + fabsf(a.y - cA.y)
                              + fabsf(a.z - cA.z);
                const float wt = (mj == 0) ? wrA.x : (mj == 1) ? wrA.y
                               : (mj == 2) ? wrA.z : wrA.w;
                const float e = ex2f(wt - C50L2E * (s * s));
                nA0 += a.w  * e;
                nA1 += vv.x * e;
                nA2 += vv.y * e;
                dA  += e;
            }
            if (r >= 1) {
                const float s = fabsf(a.x - cB.x) + fabsf(a.y - cB.y)
                              + fabsf(a.z - cB.z);
                const float wt = (mj == 0) ? wrB.x : (mj == 1) ? wrB.y
                               : (mj == 2) ? wrB.z : wrB.w;
                const float e = ex2f(wt - C50L2E * (s * s));
                nB0 += a.w  * e;
                nB1 += vv.x * e;
                nB2 += vv.y * e;
                dB  += e;
            }
        }
    }

    const float iA = rcpf(dA);
    const float iB = rcpf(dB);

    const size_t ob = (size_t)b * CH * hw + (size_t)pyA * IMG_W + px;
    out[ob]               = nA0 * iA;
    out[ob + hw]          = nA1 * iA;
    out[ob + 2 * hw]      = nA2 * iA;
    out[ob + IMG_W]           = nB0 * iB;
    out[ob + IMG_W + hw]      = nB1 * iB;
    out[ob + IMG_W + 2 * hw]  = nB2 * iB;
}

extern "C" void kernel_launch(void* const* d_in, const int* in_sizes, int n_in,
                              void* d_out, int out_size)
{
    const float* x  = (const float*)d_in[0];
    const float* g  = (const float*)d_in[1];
    const float* w0 = (const float*)d_in[2];
    float* out = (float*)d_out;

    dim3 grid(IMG_W / TW, IMG_H / TH, NB);   // 16 x 32 x 2
    dim3 block(256);
    afilt_kernel<<<grid, block>>>(x, g, w0, out);
}